// round 9
// baseline (speedup 1.0000x reference)
#include <cuda_runtime.h>
#include <cuda_bf16.h>
#include <cstdint>

#define Bb 64
#define Tt 512
#define Ii 1024
#define Hh 1024

#define RNN_CTAS 128
#define RNN_THREADS 512
// rnn smem floats: Wsh 32768 + hs 16*1024=16384 + red 16*512=8192 = 57344 (224KB)
#define RNN_SMEM_BYTES ((32768 + 16384 + 8192) * 4)

__device__ __align__(16) float g_Wih[Hh * Ii];
__device__ __align__(16) float g_bias[Hh];
__device__ __align__(16) float g_hT[2 * Hh * Bb];   // double-buffered h, [k][b]
__device__ unsigned g_flag[128];   // per-(bg,cg) producer step flags
__device__ unsigned g_done[128];
__device__ unsigned g_dummy;

typedef unsigned long long u64t;

__device__ __forceinline__ u64t pack2(float x, float y) {
    u64t r; asm("mov.b64 %0, {%1,%2};" : "=l"(r) : "f"(x), "f"(y)); return r;
}
__device__ __forceinline__ u64t fma2(u64t a, u64t b, u64t c) {
    u64t d; asm("fma.rn.f32x2 %0, %1, %2, %3;" : "=l"(d) : "l"(a), "l"(b), "l"(c)); return d;
}
__device__ __forceinline__ u64t add2(u64t a, u64t b) {
    u64t d; asm("add.rn.f32x2 %0, %1, %2;" : "=l"(d) : "l"(a), "l"(b)); return d;
}
__device__ __forceinline__ void cpasync16(uint32_t dst, const void* src) {
    asm volatile("cp.async.cg.shared.global [%0], [%1], 16;" :: "r"(dst), "l"(src));
}
#define CP_COMMIT() asm volatile("cp.async.commit_group;")

__device__ __forceinline__ void st_release(unsigned* p, unsigned v) {
    asm volatile("st.release.gpu.global.u32 [%0], %1;" :: "l"(p), "r"(v) : "memory");
}
__device__ __forceinline__ void arrive_release(unsigned* p) {
    asm volatile("red.release.gpu.global.add.u32 [%0], %1;" :: "l"(p), "r"(1u) : "memory");
}
__device__ __forceinline__ unsigned ld_acquire(unsigned* p) {
    unsigned v;
    asm volatile("ld.acquire.gpu.global.u32 %0, [%1];" : "=r"(v) : "l"(p) : "memory");
    return v;
}

__device__ __forceinline__ float hc_gate(float x) {
    float s = 1.0f / (1.0f + expf(-x));
    float v = s * 1.2f - 0.1f;
    return fminf(fmaxf(v, 0.0f), 1.0f);
}

// ---------------------------------------------------------------------------
// Phase 1: gate Wih + bias, zero h0, reset flags
// ---------------------------------------------------------------------------
__global__ void regrnn_prep(const float* __restrict__ w_ih, const float* __restrict__ w_ih_mask,
                            const float* __restrict__ b_ih, const float* __restrict__ b_ih_mask,
                            const float* __restrict__ b_hh, const float* __restrict__ b_hh_mask) {
    int i = blockIdx.x * blockDim.x + threadIdx.x;
    if (i < Hh * Ii) {
        g_Wih[i] = hc_gate(w_ih_mask[i]) * w_ih[i];
    }
    if (i < Hh) {
        g_bias[i] = hc_gate(b_ih_mask[i]) * b_ih[i] + hc_gate(b_hh_mask[i]) * b_hh[i];
    }
    if (i < 2 * Hh * Bb) g_hT[i] = 0.0f;
    if (i < 128) { g_flag[i] = 0u; g_done[i] = 0u; }
}

// launch-phase shifter: with 4 launches/call, capture index 3 -> rnn kernel
__global__ void regrnn_dummy1() { if (threadIdx.x == 1024) g_dummy = 1u; }

// ---------------------------------------------------------------------------
// Phase 2: x_proj GEMM, f32x2 packed. 128x128 tile, 8m x 8n micro. Unchanged.
// ---------------------------------------------------------------------------
__global__ void __launch_bounds__(256, 1) regrnn_xproj(const float* __restrict__ A,
                                                       float* __restrict__ out) {
    __shared__ __align__(16) float As[16][132];
    __shared__ __align__(16) float Bs[16][132];
    const int m0 = blockIdx.y * 128;
    const int n0 = blockIdx.x * 128;
    const int t = threadIdx.x;
    const int tx = t & 15;
    const int ty = t >> 4;

    u64t acc[8][4];
#pragma unroll
    for (int i = 0; i < 8; i++)
#pragma unroll
        for (int j = 0; j < 4; j++) acc[i][j] = 0ULL;

    const int mS0 = t >> 2;
    const int kS0 = (t & 3) << 2;
    const int mS1 = (t + 256) >> 2;
    const int kS1 = kS0;

    for (int kt = 0; kt < Ii; kt += 16) {
        {
            float4 v = *(const float4*)(A + (size_t)(m0 + mS0) * Ii + kt + kS0);
            As[kS0 + 0][mS0] = v.x; As[kS0 + 1][mS0] = v.y;
            As[kS0 + 2][mS0] = v.z; As[kS0 + 3][mS0] = v.w;
            v = *(const float4*)(A + (size_t)(m0 + mS1) * Ii + kt + kS1);
            As[kS1 + 0][mS1] = v.x; As[kS1 + 1][mS1] = v.y;
            As[kS1 + 2][mS1] = v.z; As[kS1 + 3][mS1] = v.w;
            v = *(const float4*)(g_Wih + (size_t)(n0 + mS0) * Ii + kt + kS0);
            Bs[kS0 + 0][mS0] = v.x; Bs[kS0 + 1][mS0] = v.y;
            Bs[kS0 + 2][mS0] = v.z; Bs[kS0 + 3][mS0] = v.w;
            v = *(const float4*)(g_Wih + (size_t)(n0 + mS1) * Ii + kt + kS1);
            Bs[kS1 + 0][mS1] = v.x; Bs[kS1 + 1][mS1] = v.y;
            Bs[kS1 + 2][mS1] = v.z; Bs[kS1 + 3][mS1] = v.w;
        }
        __syncthreads();
#pragma unroll
        for (int kk = 0; kk < 16; kk++) {
            float4 a0 = *(const float4*)&As[kk][ty << 3];
            float4 a1 = *(const float4*)&As[kk][(ty << 3) + 4];
            ulonglong2 b01 = *(const ulonglong2*)&Bs[kk][tx << 3];
            ulonglong2 b23 = *(const ulonglong2*)&Bs[kk][(tx << 3) + 4];
            float am[8] = {a0.x, a0.y, a0.z, a0.w, a1.x, a1.y, a1.z, a1.w};
#pragma unroll
            for (int mi = 0; mi < 8; mi++) {
                u64t s = pack2(am[mi], am[mi]);
                acc[mi][0] = fma2(s, b01.x, acc[mi][0]);
                acc[mi][1] = fma2(s, b01.y, acc[mi][1]);
                acc[mi][2] = fma2(s, b23.x, acc[mi][2]);
                acc[mi][3] = fma2(s, b23.y, acc[mi][3]);
            }
        }
        __syncthreads();
    }

    const int n = n0 + (tx << 3);
    ulonglong2 bv0 = *(const ulonglong2*)(g_bias + n);
    ulonglong2 bv1 = *(const ulonglong2*)(g_bias + n + 4);
#pragma unroll
    for (int i = 0; i < 8; i++) {
        int m = m0 + (ty << 3) + i;
        ulonglong2 st0, st1;
        st0.x = add2(acc[i][0], bv0.x); st0.y = add2(acc[i][1], bv0.y);
        st1.x = add2(acc[i][2], bv1.x); st1.y = add2(acc[i][3], bv1.y);
        *(ulonglong2*)(out + (size_t)m * Hh + n) = st0;
        *(ulonglong2*)(out + (size_t)m * Hh + n + 4) = st1;
    }
}

// ---------------------------------------------------------------------------
// Phase 3: persistent recurrence, batch-split (32 cg x 4 bg), 512 threads.
// NO GLOBAL BARRIER: per-producer-CTA release flags. Warp w's k-slice
// [kbase, kbase+64) comes from producers p0=kbase/32, p0+1; it waits only on
// those flags (staggered across warps), then cp.async-stages.
// Skew bound <=1 step (every CTA consumes every producer each step), so the
// 2-deep h double buffer stays race-free.
// ---------------------------------------------------------------------------
__global__ void __launch_bounds__(RNN_THREADS, 1) regrnn_rnn(
    const float* __restrict__ w_hh, const float* __restrict__ w_hh_mask,
    float* __restrict__ out)
{
    extern __shared__ __align__(16) float sm[];
    float* Wsh = sm;                    // [1024][32]
    float* hsAll = sm + 32768;          // [16 warps][4 rounds][16 k][16 b]
    float* red = sm + 32768 + 16384;    // [16][512] layout [cp8][bq][ci][b4]

    const int t = threadIdx.x;
    const int w = t >> 5;               // 0..15
    const int lane = t & 31;
    const int cg = blockIdx.x >> 2;     // col group 0..31
    const int bg = blockIdx.x & 3;      // batch group 0..3
    const int C0 = cg * 32;
    const int B0 = bg * 16;
    const int fb = bg * 32;             // flag base for this batch group

    // gate + transpose W slice into smem: Wsh[k*32 + c]
    for (int i = t; i < 8192; i += RNN_THREADS) {
        int c = i & 31;
        int k4 = (i >> 5) << 2;
        size_t base = (size_t)(C0 + c) * Ii + k4;
        float4 wv = *(const float4*)(w_hh + base);
        float4 mv = *(const float4*)(w_hh_mask + base);
        Wsh[(k4 + 0) * 32 + c] = hc_gate(mv.x) * wv.x;
        Wsh[(k4 + 1) * 32 + c] = hc_gate(mv.y) * wv.y;
        Wsh[(k4 + 2) * 32 + c] = hc_gate(mv.z) * wv.z;
        Wsh[(k4 + 3) * 32 + c] = hc_gate(mv.w) * wv.w;
    }

    const int cp8 = lane >> 2;          // col-quad 0..7
    const int bq = lane & 3;            // batch-quad 0..3
    float* hw = hsAll + w * 1024;       // this warp's 4 round-buffers (256 fl)
    uint32_t hw_u32 = (uint32_t)__cvta_generic_to_shared(hw);
    const int kbase = ((w + cg) & 15) * 64;   // 64-k slice, rotated
    const int p0 = kbase >> 5;          // producer CTA (cg) of rounds 0,1
    const int p1 = p0 + 1;              // producer of rounds 2,3

    // epilogue: one output per thread
    const int c_l = t >> 4;             // 0..31
    const int b_l = t & 15;
    const int c_g = C0 + c_l;
    const int rflat = (c_l >> 2) * 64 + (b_l >> 2) * 16 + (c_l & 3) * 4 + (b_l & 3);

    __syncthreads();

    for (int step = 0; step < Tt; step++) {
        const float* hsrc = g_hT + (step & 1) * (Hh * Bb);
        float* hdst = g_hT + ((step & 1) ^ 1) * (Hh * Bb);

        // prefetch x_proj value (independent of h)
        const int xi = ((B0 + b_l) * Tt + step) * Hh + c_g;
        float xp = __ldcs(out + xi);

        // wait producer p0's h slice, stage rounds 0,1
        while (ld_acquire(&g_flag[fb + p0]) < (unsigned)step) { }
#pragma unroll
        for (int r = 0; r < 2; r++) {
#pragma unroll
            for (int i = 0; i < 2; i++) {
                int fid = lane + (i << 5);
                int kk = fid >> 2;
                int c4 = (fid & 3) << 2;
                cpasync16(hw_u32 + ((r * 256 + kk * 16 + c4) << 2),
                          hsrc + (kbase + r * 16 + kk) * Bb + B0 + c4);
            }
            CP_COMMIT();
        }
        // wait producer p1's h slice, stage rounds 2,3
        while (ld_acquire(&g_flag[fb + p1]) < (unsigned)step) { }
#pragma unroll
        for (int r = 2; r < 4; r++) {
#pragma unroll
            for (int i = 0; i < 2; i++) {
                int fid = lane + (i << 5);
                int kk = fid >> 2;
                int c4 = (fid & 3) << 2;
                cpasync16(hw_u32 + ((r * 256 + kk * 16 + c4) << 2),
                          hsrc + (kbase + r * 16 + kk) * Bb + B0 + c4);
            }
            CP_COMMIT();
        }

        u64t acc[4][2];
#pragma unroll
        for (int i = 0; i < 4; i++) { acc[i][0] = 0ULL; acc[i][1] = 0ULL; }

#pragma unroll
        for (int r = 0; r < 4; r++) {
            switch (r) {
                case 0: asm volatile("cp.async.wait_group 3;"); break;
                case 1: asm volatile("cp.async.wait_group 2;"); break;
                case 2: asm volatile("cp.async.wait_group 1;"); break;
                default: asm volatile("cp.async.wait_group 0;"); break;
            }
            __syncwarp();
            const float* hb = hw + r * 256;
            const int kr = kbase + r * 16;
#pragma unroll
            for (int kk = 0; kk < 16; kk++) {
                float4 w4 = *(const float4*)&Wsh[(kr + kk) * 32 + (cp8 << 2)];
                ulonglong2 h2 = *(const ulonglong2*)&hb[kk * 16 + (bq << 2)];
                u64t s0 = pack2(w4.x, w4.x);
                u64t s1 = pack2(w4.y, w4.y);
                u64t s2 = pack2(w4.z, w4.z);
                u64t s3 = pack2(w4.w, w4.w);
                acc[0][0] = fma2(s0, h2.x, acc[0][0]); acc[0][1] = fma2(s0, h2.y, acc[0][1]);
                acc[1][0] = fma2(s1, h2.x, acc[1][0]); acc[1][1] = fma2(s1, h2.y, acc[1][1]);
                acc[2][0] = fma2(s2, h2.x, acc[2][0]); acc[2][1] = fma2(s2, h2.y, acc[2][1]);
                acc[3][0] = fma2(s3, h2.x, acc[3][0]); acc[3][1] = fma2(s3, h2.y, acc[3][1]);
            }
        }

        // K-split partials, conflict-free: red[w][cp8][bq][ci][b4]
        {
            float* rw = red + w * 512 + (cp8 << 6) + (bq << 4);
#pragma unroll
            for (int ci = 0; ci < 4; ci++) {
                ulonglong2 v; v.x = acc[ci][0]; v.y = acc[ci][1];
                *(ulonglong2*)&rw[ci << 2] = v;
            }
        }
        __syncthreads();   // sync1: partials visible

        // reduce 16 partials, tanh, write next h
        float s = 0.0f;
#pragma unroll
        for (int ww = 0; ww < 16; ww++) s += red[ww * 512 + rflat];
        float hv = tanhf(xp + s);
        if (step < Tt - 1) __stcg(hdst + c_g * Bb + B0 + b_l, hv);

        __syncthreads();   // sync2: h stores done block-wide; also guards red reuse

        // publish this CTA's h slice for step+1 consumers
        if (t == 0 && step < Tt - 1) st_release(&g_flag[fb + cg], (unsigned)(step + 1));

        // out writes off the critical path
        __stcs(out + xi, hv);
        if (step == Tt - 1) {
            out[Bb * Tt * Hh + (B0 + b_l) * Hh + c_g] = hv;
        }
    }

    // exit protocol: reset flags for next graph replay
    if (t == 0) {
        unsigned* done = &g_done[bg * 32];
        arrive_release(done);
        if (cg == 0) {
            while (ld_acquire(done) < 32u) { }
#pragma unroll
            for (int i = 0; i < 32; i++) g_flag[fb + i] = 0u;
            *done = 0u;
        }
    }
}

// ---------------------------------------------------------------------------
extern "C" void kernel_launch(void* const* d_in, const int* in_sizes, int n_in,
                              void* d_out, int out_size) {
    (void)in_sizes; (void)n_in; (void)out_size;
    const float* seq       = (const float*)d_in[0];
    const float* w_ih      = (const float*)d_in[1];
    const float* w_ih_mask = (const float*)d_in[2];
    const float* w_hh      = (const float*)d_in[3];
    const float* w_hh_mask = (const float*)d_in[4];
    const float* b_ih      = (const float*)d_in[5];
    const float* b_ih_mask = (const float*)d_in[6];
    const float* b_hh      = (const float*)d_in[7];
    const float* b_hh_mask = (const float*)d_in[8];
    float* out = (float*)d_out;

    regrnn_prep<<<(Hh * Ii + 255) / 256, 256>>>(w_ih, w_ih_mask,
                                                b_ih, b_ih_mask, b_hh, b_hh_mask);
    regrnn_dummy1<<<1, 32>>>();
    regrnn_xproj<<<dim3(Hh / 128, (Bb * Tt) / 128), 256>>>(seq, out);

    cudaFuncSetAttribute(regrnn_rnn, cudaFuncAttributeMaxDynamicSharedMemorySize, RNN_SMEM_BYTES);
    regrnn_rnn<<<RNN_CTAS, RNN_THREADS, RNN_SMEM_BYTES>>>(w_hh, w_hh_mask, out);
}

// round 10
// speedup vs baseline: 1.4684x; 1.4684x over previous
#include <cuda_runtime.h>
#include <cuda_bf16.h>
#include <cstdint>

#define Bb 64
#define Tt 512
#define Ii 1024
#define Hh 1024

#define RNN_CTAS 128
// rnn smem floats: Wsh 32768 + hs 8*4*512=16384 + red 8*512=4096 = 53248 (208KB)
#define RNN_SMEM_BYTES ((32768 + 16384 + 4096) * 4)

__device__ __align__(16) float g_Wih[Hh * Ii];
__device__ __align__(16) float g_bias[Hh];
__device__ __align__(16) float g_hT[2 * Hh * Bb];   // double-buffered h, [k][b]
__device__ unsigned g_cnt[128];    // 4 barrier groups, stride 32 (128B apart)
__device__ unsigned g_done[128];
__device__ unsigned g_dummy;

typedef unsigned long long u64t;

__device__ __forceinline__ u64t pack2(float x, float y) {
    u64t r; asm("mov.b64 %0, {%1,%2};" : "=l"(r) : "f"(x), "f"(y)); return r;
}
__device__ __forceinline__ u64t fma2(u64t a, u64t b, u64t c) {
    u64t d; asm("fma.rn.f32x2 %0, %1, %2, %3;" : "=l"(d) : "l"(a), "l"(b), "l"(c)); return d;
}
__device__ __forceinline__ u64t add2(u64t a, u64t b) {
    u64t d; asm("add.rn.f32x2 %0, %1, %2;" : "=l"(d) : "l"(a), "l"(b)); return d;
}
__device__ __forceinline__ void cpasync16(uint32_t dst, const void* src) {
    asm volatile("cp.async.cg.shared.global [%0], [%1], 16;" :: "r"(dst), "l"(src));
}
#define CP_COMMIT() asm volatile("cp.async.commit_group;")

__device__ __forceinline__ void arrive_release(unsigned* p) {
    asm volatile("red.release.gpu.global.add.u32 [%0], %1;" :: "l"(p), "r"(1u) : "memory");
}
__device__ __forceinline__ unsigned ld_acquire(unsigned* p) {
    unsigned v;
    asm volatile("ld.acquire.gpu.global.u32 %0, [%1];" : "=r"(v) : "l"(p) : "memory");
    return v;
}

__device__ __forceinline__ float hc_gate(float x) {
    float s = 1.0f / (1.0f + expf(-x));
    float v = s * 1.2f - 0.1f;
    return fminf(fmaxf(v, 0.0f), 1.0f);
}

// ---------------------------------------------------------------------------
// Phase 1: gate Wih + bias, zero h0, reset barrier counters
// ---------------------------------------------------------------------------
__global__ void regrnn_prep(const float* __restrict__ w_ih, const float* __restrict__ w_ih_mask,
                            const float* __restrict__ b_ih, const float* __restrict__ b_ih_mask,
                            const float* __restrict__ b_hh, const float* __restrict__ b_hh_mask) {
    int i = blockIdx.x * blockDim.x + threadIdx.x;
    if (i < Hh * Ii) {
        g_Wih[i] = hc_gate(w_ih_mask[i]) * w_ih[i];
    }
    if (i < Hh) {
        g_bias[i] = hc_gate(b_ih_mask[i]) * b_ih[i] + hc_gate(b_hh_mask[i]) * b_hh[i];
    }
    if (i < 2 * Hh * Bb) g_hT[i] = 0.0f;
    if (i < 128) { g_cnt[i] = 0u; g_done[i] = 0u; }
}

// phase shifters: 5 launches/call -> ncu capture index 3 = xproj
__global__ void regrnn_dummy1() { if (threadIdx.x == 1024) g_dummy = 1u; }
__global__ void regrnn_dummy2() { if (threadIdx.x == 1024) g_dummy = 2u; }

// ---------------------------------------------------------------------------
// Phase 2: x_proj GEMM, f32x2 packed. 128x128 tile, 8m x 8n micro.
// Software pipeline: next k-tile's LDGs issued right after staging sync and
// consumed next iteration (latency off the critical path).
// __launch_bounds__(256, 2): cap regs at 128 -> 2 CTAs/SM.
// ---------------------------------------------------------------------------
__global__ void __launch_bounds__(256, 2) regrnn_xproj(const float* __restrict__ A,
                                                       float* __restrict__ out) {
    __shared__ __align__(16) float As[16][132];
    __shared__ __align__(16) float Bs[16][132];
    const int m0 = blockIdx.y * 128;
    const int n0 = blockIdx.x * 128;
    const int t = threadIdx.x;
    const int tx = t & 15;    // n-oct
    const int ty = t >> 4;    // m-oct

    u64t acc[8][4];
#pragma unroll
    for (int i = 0; i < 8; i++)
#pragma unroll
        for (int j = 0; j < 4; j++) acc[i][j] = 0ULL;

    const int mS0 = t >> 2;            // 0..63
    const int kS0 = (t & 3) << 2;
    const int mS1 = mS0 + 64;          // 64..127

    const float* pA0 = A + (size_t)(m0 + mS0) * Ii + kS0;
    const float* pA1 = A + (size_t)(m0 + mS1) * Ii + kS0;
    const float* pB0 = g_Wih + (size_t)(n0 + mS0) * Ii + kS0;
    const float* pB1 = g_Wih + (size_t)(n0 + mS1) * Ii + kS0;

    // prefetch tile 0
    float4 a0v = *(const float4*)(pA0);
    float4 a1v = *(const float4*)(pA1);
    float4 b0v = *(const float4*)(pB0);
    float4 b1v = *(const float4*)(pB1);

    for (int kt = 0; kt < Ii; kt += 16) {
        // stage current tile (regs -> smem, transposed)
        As[kS0 + 0][mS0] = a0v.x; As[kS0 + 1][mS0] = a0v.y;
        As[kS0 + 2][mS0] = a0v.z; As[kS0 + 3][mS0] = a0v.w;
        As[kS0 + 0][mS1] = a1v.x; As[kS0 + 1][mS1] = a1v.y;
        As[kS0 + 2][mS1] = a1v.z; As[kS0 + 3][mS1] = a1v.w;
        Bs[kS0 + 0][mS0] = b0v.x; Bs[kS0 + 1][mS0] = b0v.y;
        Bs[kS0 + 2][mS0] = b0v.z; Bs[kS0 + 3][mS0] = b0v.w;
        Bs[kS0 + 0][mS1] = b1v.x; Bs[kS0 + 1][mS1] = b1v.y;
        Bs[kS0 + 2][mS1] = b1v.z; Bs[kS0 + 3][mS1] = b1v.w;
        __syncthreads();

        // prefetch next tile (overlaps with compute below)
        if (kt + 16 < Ii) {
            a0v = *(const float4*)(pA0 + kt + 16);
            a1v = *(const float4*)(pA1 + kt + 16);
            b0v = *(const float4*)(pB0 + kt + 16);
            b1v = *(const float4*)(pB1 + kt + 16);
        }

#pragma unroll
        for (int kk = 0; kk < 16; kk++) {
            float4 a0 = *(const float4*)&As[kk][ty << 3];
            float4 a1 = *(const float4*)&As[kk][(ty << 3) + 4];
            ulonglong2 b01 = *(const ulonglong2*)&Bs[kk][tx << 3];
            ulonglong2 b23 = *(const ulonglong2*)&Bs[kk][(tx << 3) + 4];
            float am[8] = {a0.x, a0.y, a0.z, a0.w, a1.x, a1.y, a1.z, a1.w};
#pragma unroll
            for (int mi = 0; mi < 8; mi++) {
                u64t s = pack2(am[mi], am[mi]);
                acc[mi][0] = fma2(s, b01.x, acc[mi][0]);
                acc[mi][1] = fma2(s, b01.y, acc[mi][1]);
                acc[mi][2] = fma2(s, b23.x, acc[mi][2]);
                acc[mi][3] = fma2(s, b23.y, acc[mi][3]);
            }
        }
        __syncthreads();
    }

    const int n = n0 + (tx << 3);
    ulonglong2 bv0 = *(const ulonglong2*)(g_bias + n);
    ulonglong2 bv1 = *(const ulonglong2*)(g_bias + n + 4);
#pragma unroll
    for (int i = 0; i < 8; i++) {
        int m = m0 + (ty << 3) + i;
        ulonglong2 st0, st1;
        st0.x = add2(acc[i][0], bv0.x); st0.y = add2(acc[i][1], bv0.y);
        st1.x = add2(acc[i][2], bv1.x); st1.y = add2(acc[i][3], bv1.y);
        *(ulonglong2*)(out + (size_t)m * Hh + n) = st0;
        *(ulonglong2*)(out + (size_t)m * Hh + n + 4) = st1;
    }
}

// ---------------------------------------------------------------------------
// Phase 3: persistent recurrence — R7 configuration (best known: 256 threads,
// 8 warps K-split, quad-buffered staging, single-counter barrier) + next-step
// x_proj prefetch carried in registers.
// ---------------------------------------------------------------------------
__global__ void __launch_bounds__(256, 1) regrnn_rnn(
    const float* __restrict__ w_hh, const float* __restrict__ w_hh_mask,
    float* __restrict__ out)
{
    extern __shared__ __align__(16) float sm[];
    float* Wsh = sm;                    // [1024][32]
    float* hsAll = sm + 32768;          // [8 warps][4 rounds][32 k][16 b]
    float* red = sm + 32768 + 16384;    // [8][512] layout [cp8][bq][ci][b4]

    const int t = threadIdx.x;
    const int w = t >> 5;
    const int lane = t & 31;
    const int cg = blockIdx.x >> 2;     // col group 0..31
    const int bg = blockIdx.x & 3;      // batch group 0..3
    const int C0 = cg * 32;
    const int B0 = bg * 16;

    // gate + transpose W slice into smem
    for (int i = t; i < 8192; i += 256) {
        int c = i & 31;
        int k4 = (i >> 5) << 2;
        size_t base = (size_t)(C0 + c) * Ii + k4;
        float4 wv = *(const float4*)(w_hh + base);
        float4 mv = *(const float4*)(w_hh_mask + base);
        Wsh[(k4 + 0) * 32 + c] = hc_gate(mv.x) * wv.x;
        Wsh[(k4 + 1) * 32 + c] = hc_gate(mv.y) * wv.y;
        Wsh[(k4 + 2) * 32 + c] = hc_gate(mv.z) * wv.z;
        Wsh[(k4 + 3) * 32 + c] = hc_gate(mv.w) * wv.w;
    }

    const int cp8 = lane >> 2;          // col-quad 0..7
    const int bq = lane & 3;            // batch-quad 0..3
    float* hw = hsAll + w * 2048;       // this warp's 4 round-buffers (512 fl)
    uint32_t hw_u32 = (uint32_t)__cvta_generic_to_shared(hw);
    const int kbase = ((w + cg) & 7) * 128;

    const int o0 = 2 * t;
    const int c_l = o0 >> 4;
    const int b_l = o0 & 15;
    const int c_g = C0 + c_l;
    const int rflat = (c_l >> 2) * 64 + (b_l >> 2) * 16 + (c_l & 3) * 4 + (b_l & 3);

    unsigned* cnt = &g_cnt[bg * 32];

    // x_proj base indices (advance by Hh per step)
    int xi0 = ((B0 + b_l) * Tt) * Hh + c_g;
    int xi1 = ((B0 + b_l + 1) * Tt) * Hh + c_g;

    __syncthreads();

    // prefetch step-0 x_proj
    float xp0 = __ldcs(out + xi0);
    float xp1 = __ldcs(out + xi1);

    for (int step = 0; step < Tt; step++) {
        const float* hsrc = g_hT + (step & 1) * (Hh * Bb);
        float* hdst = g_hT + ((step & 1) ^ 1) * (Hh * Bb);

        // stage ALL 4 rounds (quad-buffered, one commit group per round)
#pragma unroll
        for (int r = 0; r < 4; r++) {
#pragma unroll
            for (int i = 0; i < 4; i++) {
                int fid = lane + (i << 5);
                int kk = fid >> 2;
                int c4 = (fid & 3) << 2;
                cpasync16(hw_u32 + ((r * 512 + kk * 16 + c4) << 2),
                          hsrc + (kbase + r * 32 + kk) * Bb + B0 + c4);
            }
            CP_COMMIT();
        }

        // prefetch NEXT step's x_proj (overlaps with compute below)
        float nxp0 = 0.0f, nxp1 = 0.0f;
        if (step + 1 < Tt) {
            nxp0 = __ldcs(out + xi0 + Hh);
            nxp1 = __ldcs(out + xi1 + Hh);
        }

        u64t acc[4][2];
#pragma unroll
        for (int i = 0; i < 4; i++) { acc[i][0] = 0ULL; acc[i][1] = 0ULL; }

#pragma unroll
        for (int r = 0; r < 4; r++) {
            switch (r) {
                case 0: asm volatile("cp.async.wait_group 3;"); break;
                case 1: asm volatile("cp.async.wait_group 2;"); break;
                case 2: asm volatile("cp.async.wait_group 1;"); break;
                default: asm volatile("cp.async.wait_group 0;"); break;
            }
            __syncwarp();
            const float* hb = hw + r * 512;
            const int kr = kbase + r * 32;
#pragma unroll
            for (int kk = 0; kk < 32; kk++) {
                float4 w4 = *(const float4*)&Wsh[(kr + kk) * 32 + (cp8 << 2)];
                ulonglong2 h2 = *(const ulonglong2*)&hb[kk * 16 + (bq << 2)];
                u64t s0 = pack2(w4.x, w4.x);
                u64t s1 = pack2(w4.y, w4.y);
                u64t s2 = pack2(w4.z, w4.z);
                u64t s3 = pack2(w4.w, w4.w);
                acc[0][0] = fma2(s0, h2.x, acc[0][0]); acc[0][1] = fma2(s0, h2.y, acc[0][1]);
                acc[1][0] = fma2(s1, h2.x, acc[1][0]); acc[1][1] = fma2(s1, h2.y, acc[1][1]);
                acc[2][0] = fma2(s2, h2.x, acc[2][0]); acc[2][1] = fma2(s2, h2.y, acc[2][1]);
                acc[3][0] = fma2(s3, h2.x, acc[3][0]); acc[3][1] = fma2(s3, h2.y, acc[3][1]);
            }
        }

        // K-split partials, conflict-free: red[w][cp8][bq][ci][b4]
        {
            float* rw = red + w * 512 + (cp8 << 6) + (bq << 4);
#pragma unroll
            for (int ci = 0; ci < 4; ci++) {
                ulonglong2 v; v.x = acc[ci][0]; v.y = acc[ci][1];
                *(ulonglong2*)&rw[ci << 2] = v;
            }
        }
        __syncthreads();

        // reduce 8 partials, tanh, write next h
        float sx = 0.0f, sy = 0.0f;
#pragma unroll
        for (int ww = 0; ww < 8; ww++) {
            float2 v = *(const float2*)&red[ww * 512 + rflat];
            sx += v.x; sy += v.y;
        }
        float hv0 = tanhf(xp0 + sx);
        float hv1 = tanhf(xp1 + sy);
        __stcg((float2*)(hdst + c_g * Bb + B0 + b_l), make_float2(hv0, hv1));

        __syncthreads();   // h stores HB-before t0's release
        if (t == 0 && step < Tt - 1) {
            arrive_release(cnt);
            unsigned target = 32u * (unsigned)(step + 1);
            while (ld_acquire(cnt) < target) { }
        }
        // out writes overlap t0's spin
        __stcs(out + xi0, hv0);
        __stcs(out + xi1, hv1);
        if (step == Tt - 1) {
            out[Bb * Tt * Hh + (B0 + b_l) * Hh + c_g] = hv0;
            out[Bb * Tt * Hh + (B0 + b_l + 1) * Hh + c_g] = hv1;
        }
        xp0 = nxp0; xp1 = nxp1;
        xi0 += Hh; xi1 += Hh;
        __syncthreads();
    }

    // exit protocol: reset counters for next graph replay
    if (t == 0) {
        unsigned* done = &g_done[bg * 32];
        arrive_release(done);
        if (cg == 0) {
            while (ld_acquire(done) < 32u) { }
            *cnt = 0u;
            *done = 0u;
        }
    }
}

// ---------------------------------------------------------------------------
extern "C" void kernel_launch(void* const* d_in, const int* in_sizes, int n_in,
                              void* d_out, int out_size) {
    (void)in_sizes; (void)n_in; (void)out_size;
    const float* seq       = (const float*)d_in[0];
    const float* w_ih      = (const float*)d_in[1];
    const float* w_ih_mask = (const float*)d_in[2];
    const float* w_hh      = (const float*)d_in[3];
    const float* w_hh_mask = (const float*)d_in[4];
    const float* b_ih      = (const float*)d_in[5];
    const float* b_ih_mask = (const float*)d_in[6];
    const float* b_hh      = (const float*)d_in[7];
    const float* b_hh_mask = (const float*)d_in[8];
    float* out = (float*)d_out;

    regrnn_prep<<<(Hh * Ii + 255) / 256, 256>>>(w_ih, w_ih_mask,
                                                b_ih, b_ih_mask, b_hh, b_hh_mask);
    regrnn_dummy1<<<1, 32>>>();
    regrnn_dummy2<<<1, 32>>>();
    regrnn_xproj<<<dim3(Hh / 128, (Bb * Tt) / 128), 256>>>(seq, out);

    cudaFuncSetAttribute(regrnn_rnn, cudaFuncAttributeMaxDynamicSharedMemorySize, RNN_SMEM_BYTES);
    regrnn_rnn<<<RNN_CTAS, 256, RNN_SMEM_BYTES>>>(w_hh, w_hh_mask, out);
}